// round 1
// baseline (speedup 1.0000x reference)
#include <cuda_runtime.h>
#include <cstdint>

// Causal flash attention, B=2 S=2048 H=16 D=128, fp32 in/out.
// TF32 mma.sync.m16n8k8 path: Q fragments + O accumulators in registers,
// K/V tiles in padded SMEM, online softmax, causal tile pruning.

namespace {
constexpr int Bc = 2, Sc = 2048, Hc = 16, Dc = 128;
constexpr int BM = 64;          // q rows per block (16 per warp x 4 warps)
constexpr int BN = 32;          // keys per KV tile
constexpr int KSTRIDE = Dc + 4; // 132: conflict-free K B-frag gathers
constexpr int VSTRIDE = Dc + 8; // 136: conflict-free V B-frag gathers
constexpr int HD = Hc * Dc;     // 2048: stride between consecutive seq rows

__device__ __forceinline__ uint32_t f2tf(float x) {
    uint32_t u; asm("cvt.rna.tf32.f32 %0, %1;" : "=r"(u) : "f"(x)); return u;
}
__device__ __forceinline__ float rtf(float x) {
    uint32_t u; asm("cvt.rna.tf32.f32 %0, %1;" : "=r"(u) : "f"(x));
    return __uint_as_float(u);
}
__device__ __forceinline__ float ex2f(float x) {
    float y; asm("ex2.approx.f32 %0, %1;" : "=f"(y) : "f"(x)); return y;
}
__device__ __forceinline__ void mma8(float c[4], const uint32_t a[4],
                                     uint32_t b0, uint32_t b1) {
    asm volatile(
        "mma.sync.aligned.m16n8k8.row.col.f32.tf32.tf32.f32 "
        "{%0,%1,%2,%3}, {%4,%5,%6,%7}, {%8,%9}, {%0,%1,%2,%3};"
        : "+f"(c[0]), "+f"(c[1]), "+f"(c[2]), "+f"(c[3])
        : "r"(a[0]), "r"(a[1]), "r"(a[2]), "r"(a[3]), "r"(b0), "r"(b1));
}
} // namespace

__global__ __launch_bounds__(128) void fa_tf32_kernel(
    const float* __restrict__ Q, const float* __restrict__ K,
    const float* __restrict__ V, float* __restrict__ O)
{
    __shared__ float Ks[BN * KSTRIDE];
    __shared__ float Vs[BN * VSTRIDE];

    const int tid  = threadIdx.x;
    const int warp = tid >> 5;
    const int lane = tid & 31;
    const int g = lane >> 2;   // group (quad) id: 0..7
    const int t = lane & 3;    // thread-in-group: 0..3

    const int qtile = blockIdx.x;
    const int bh = blockIdx.y;
    const int b = bh >> 4;     // / H
    const int h = bh & 15;     // % H

    const int q0 = qtile * BM + warp * 16;  // this warp's first q row

    // fold 1/sqrt(D) and log2(e) into Q so softmax uses ex2 directly
    const float scale = 0.08838834764831845f * 1.4426950408889634f;

    // ---- Q fragments: 16 rows x 128 cols as 16 k-chunks of m16n8k8 A frags
    uint32_t qa[16][4];
    {
        const float* qp = Q + ((size_t)(b * Sc + q0) * Hc + h) * Dc;
        #pragma unroll
        for (int c = 0; c < 16; ++c) {
            int d0 = c * 8 + t;
            qa[c][0] = f2tf(qp[(size_t)g       * HD + d0    ] * scale);
            qa[c][1] = f2tf(qp[(size_t)(g + 8) * HD + d0    ] * scale);
            qa[c][2] = f2tf(qp[(size_t)g       * HD + d0 + 4] * scale);
            qa[c][3] = f2tf(qp[(size_t)(g + 8) * HD + d0 + 4] * scale);
        }
    }

    // ---- O accumulators: 16 rows x 128 cols as 16 n-tiles of C frags
    float o[16][4];
    #pragma unroll
    for (int i = 0; i < 16; ++i) { o[i][0]=0.f; o[i][1]=0.f; o[i][2]=0.f; o[i][3]=0.f; }
    float m0 = -1e30f, m1 = -1e30f, l0 = 0.f, l1 = 0.f;

    const int nkt = 2 * qtile + 2;  // causal: only tiles with key <= q_end
    const float* kbase = K + ((size_t)(b * Sc) * Hc + h) * Dc;
    const float* vbase = V + ((size_t)(b * Sc) * Hc + h) * Dc;

    for (int kt = 0; kt < nkt; ++kt) {
        const int kv0 = kt * BN;

        __syncthreads();  // previous tile fully consumed
        {
            const float* kp = kbase + (size_t)kv0 * HD;
            const float* vp = vbase + (size_t)kv0 * HD;
            #pragma unroll
            for (int p = 0; p < 8; ++p) {
                int lin = (p * 128 + tid) * 4;
                int key = lin >> 7;
                int d   = lin & 127;
                float4 kk = *reinterpret_cast<const float4*>(kp + (size_t)key * HD + d);
                float4 vv = *reinterpret_cast<const float4*>(vp + (size_t)key * HD + d);
                // round-to-nearest tf32 once here (avoids HW truncation bias)
                kk.x = rtf(kk.x); kk.y = rtf(kk.y); kk.z = rtf(kk.z); kk.w = rtf(kk.w);
                vv.x = rtf(vv.x); vv.y = rtf(vv.y); vv.z = rtf(vv.z); vv.w = rtf(vv.w);
                *reinterpret_cast<float4*>(&Ks[key * KSTRIDE + d]) = kk;
                *reinterpret_cast<float4*>(&Vs[key * VSTRIDE + d]) = vv;
            }
        }
        __syncthreads();

        // ---- S = Q K^T : 4 n-tiles (8 keys each) x 16 k-chunks
        float sc[4][4];
        #pragma unroll
        for (int nt = 0; nt < 4; ++nt) {
            sc[nt][0]=0.f; sc[nt][1]=0.f; sc[nt][2]=0.f; sc[nt][3]=0.f;
            const float* krow = &Ks[(nt * 8 + g) * KSTRIDE];
            #pragma unroll
            for (int c = 0; c < 16; ++c) {
                uint32_t b0 = __float_as_uint(krow[c * 8 + t]);
                uint32_t b1 = __float_as_uint(krow[c * 8 + t + 4]);
                mma8(sc[nt], qa[c], b0, b1);
            }
        }

        // ---- causal mask (only tiles touching/above the diagonal)
        if (kv0 + BN - 1 > q0) {
            #pragma unroll
            for (int nt = 0; nt < 4; ++nt) {
                int kb = kv0 + nt * 8 + 2 * t;
                if (kb     > q0 + g)     sc[nt][0] = -1e30f;
                if (kb + 1 > q0 + g)     sc[nt][1] = -1e30f;
                if (kb     > q0 + g + 8) sc[nt][2] = -1e30f;
                if (kb + 1 > q0 + g + 8) sc[nt][3] = -1e30f;
            }
        }

        // ---- online softmax (rows g and g+8 per thread)
        float mg0 = -1e30f, mg1 = -1e30f;
        #pragma unroll
        for (int nt = 0; nt < 4; ++nt) {
            mg0 = fmaxf(mg0, fmaxf(sc[nt][0], sc[nt][1]));
            mg1 = fmaxf(mg1, fmaxf(sc[nt][2], sc[nt][3]));
        }
        mg0 = fmaxf(mg0, __shfl_xor_sync(0xffffffffu, mg0, 1));
        mg0 = fmaxf(mg0, __shfl_xor_sync(0xffffffffu, mg0, 2));
        mg1 = fmaxf(mg1, __shfl_xor_sync(0xffffffffu, mg1, 1));
        mg1 = fmaxf(mg1, __shfl_xor_sync(0xffffffffu, mg1, 2));

        float m0n = fmaxf(m0, mg0);
        float m1n = fmaxf(m1, mg1);
        float a0 = ex2f(m0 - m0n);
        float a1 = ex2f(m1 - m1n);
        m0 = m0n; m1 = m1n;

        float r0 = 0.f, r1 = 0.f;
        #pragma unroll
        for (int nt = 0; nt < 4; ++nt) {
            sc[nt][0] = ex2f(sc[nt][0] - m0n);
            sc[nt][1] = ex2f(sc[nt][1] - m0n);
            sc[nt][2] = ex2f(sc[nt][2] - m1n);
            sc[nt][3] = ex2f(sc[nt][3] - m1n);
            r0 += sc[nt][0] + sc[nt][1];
            r1 += sc[nt][2] + sc[nt][3];
        }
        r0 += __shfl_xor_sync(0xffffffffu, r0, 1);
        r0 += __shfl_xor_sync(0xffffffffu, r0, 2);
        r1 += __shfl_xor_sync(0xffffffffu, r1, 1);
        r1 += __shfl_xor_sync(0xffffffffu, r1, 2);
        l0 = l0 * a0 + r0;
        l1 = l1 * a1 + r1;

        #pragma unroll
        for (int i = 0; i < 16; ++i) {
            o[i][0] *= a0; o[i][1] *= a0;
            o[i][2] *= a1; o[i][3] *= a1;
        }

        // ---- O += P V : remap C-layout P (cols {2t,2t+1}) to A-layout (cols {t,t+4})
        #pragma unroll
        for (int kc = 0; kc < 4; ++kc) {
            int src = (lane & ~3) | (t >> 1);
            float v0 = __shfl_sync(0xffffffffu, sc[kc][0], src);
            float v1 = __shfl_sync(0xffffffffu, sc[kc][1], src);
            float v2 = __shfl_sync(0xffffffffu, sc[kc][2], src);
            float v3 = __shfl_sync(0xffffffffu, sc[kc][3], src);
            float w0 = __shfl_sync(0xffffffffu, sc[kc][0], src + 2);
            float w1 = __shfl_sync(0xffffffffu, sc[kc][1], src + 2);
            float w2 = __shfl_sync(0xffffffffu, sc[kc][2], src + 2);
            float w3 = __shfl_sync(0xffffffffu, sc[kc][3], src + 2);
            uint32_t pa[4];
            bool odd = (t & 1) != 0;
            pa[0] = f2tf(odd ? v1 : v0);  // (row g,   key t)
            pa[1] = f2tf(odd ? v3 : v2);  // (row g+8, key t)
            pa[2] = f2tf(odd ? w1 : w0);  // (row g,   key t+4)
            pa[3] = f2tf(odd ? w3 : w2);  // (row g+8, key t+4)
            const float* vrow0 = &Vs[(kc * 8 + t)     * VSTRIDE];
            const float* vrow1 = &Vs[(kc * 8 + t + 4) * VSTRIDE];
            #pragma unroll
            for (int ot = 0; ot < 16; ++ot) {
                uint32_t b0 = __float_as_uint(vrow0[ot * 8 + g]);
                uint32_t b1 = __float_as_uint(vrow1[ot * 8 + g]);
                mma8(o[ot], pa, b0, b1);
            }
        }
    }

    // ---- normalize + store
    float inv0 = __frcp_rn(l0);
    float inv1 = __frcp_rn(l1);
    float* op = O + ((size_t)(b * Sc + q0) * Hc + h) * Dc;
    #pragma unroll
    for (int ot = 0; ot < 16; ++ot) {
        int d = ot * 8 + 2 * t;
        float2 r0v = make_float2(o[ot][0] * inv0, o[ot][1] * inv0);
        float2 r1v = make_float2(o[ot][2] * inv1, o[ot][3] * inv1);
        *reinterpret_cast<float2*>(op + (size_t)g       * HD + d) = r0v;
        *reinterpret_cast<float2*>(op + (size_t)(g + 8) * HD + d) = r1v;
    }
}

extern "C" void kernel_launch(void* const* d_in, const int* in_sizes, int n_in,
                              void* d_out, int out_size) {
    (void)in_sizes; (void)n_in; (void)out_size;
    const float* q = (const float*)d_in[0];
    const float* k = (const float*)d_in[1];
    const float* v = (const float*)d_in[2];
    float* out = (float*)d_out;
    dim3 grid(Sc / BM, Bc * Hc);
    fa_tf32_kernel<<<grid, 128>>>(q, k, v, out);
}

// round 3
// speedup vs baseline: 1.1453x; 1.1453x over previous
#include <cuda_runtime.h>
#include <cstdint>

// Causal flash attention, B=2 S=2048 H=16 D=128, fp32 in/out.
// Prepass packs K/V into head-major, tf32-rounded, fragment-permuted scratch;
// main kernel: cp.async double buffering + vectorized LDS fragment gathers.

namespace {
constexpr int Bc = 2, Sc = 2048, Hc = 16, Dc = 128;
constexpr int BM = 64;          // q rows per block (16 per warp x 4 warps)
constexpr int BN = 32;          // keys per KV tile
constexpr int KS = 136;         // K smem row stride (floats): LDS.64 conflict-free
constexpr int VS = 132;         // V smem row stride (floats): LDS.128 conflict-free
constexpr int HD = Hc * Dc;     // 2048 floats between seq rows in [B,S,H,D]
constexpr int BUFF = BN * KS + BN * VS;          // floats per pipeline buffer
constexpr int SMEM_BYTES = 2 * BUFF * 4;         // 68608 B

__device__ float g_Kf[(size_t)Bc * Hc * Sc * Dc];
__device__ float g_Vf[(size_t)Bc * Hc * Sc * Dc];

__device__ __forceinline__ uint32_t f2tf(float x) {
    uint32_t u; asm("cvt.rna.tf32.f32 %0, %1;" : "=r"(u) : "f"(x)); return u;
}
__device__ __forceinline__ float ex2f(float x) {
    float y; asm("ex2.approx.f32 %0, %1;" : "=f"(y) : "f"(x)); return y;
}
__device__ __forceinline__ void mma8(float c[4], const uint32_t a[4],
                                     uint32_t b0, uint32_t b1) {
    asm volatile(
        "mma.sync.aligned.m16n8k8.row.col.f32.tf32.tf32.f32 "
        "{%0,%1,%2,%3}, {%4,%5,%6,%7}, {%8,%9}, {%0,%1,%2,%3};"
        : "+f"(c[0]), "+f"(c[1]), "+f"(c[2]), "+f"(c[3])
        : "r"(a[0]), "r"(a[1]), "r"(a[2]), "r"(a[3]), "r"(b0), "r"(b1));
}
__device__ __forceinline__ void cpa16(uint32_t dst, const void* src) {
    asm volatile("cp.async.cg.shared.global [%0], [%1], 16;"
                 :: "r"(dst), "l"(src));
}
} // namespace

// ---------------- prepass: [B,S,H,D] -> head-major + tf32 RNA + frag perm ----
// One block handles 8 source rows of K AND the same 8 rows of V.
__global__ __launch_bounds__(256) void prep_kernel(
    const float* __restrict__ K, const float* __restrict__ V)
{
    __shared__ float stK[8 * 128];
    __shared__ float stV[8 * 128];
    const int rg = blockIdx.x;             // group of 8 source rows
    const int tid = threadIdx.x;

    {
        const float4* k4 = reinterpret_cast<const float4*>(K + (size_t)rg * 8 * 128);
        const float4* v4 = reinterpret_cast<const float4*>(V + (size_t)rg * 8 * 128);
        *reinterpret_cast<float4*>(&stK[tid * 4]) = k4[tid];
        *reinterpret_cast<float4*>(&stV[tid * 4]) = v4[tid];
    }
    __syncthreads();

    const int lr = tid >> 5;               // local row 0..7
    const int j0 = (tid & 31) * 4;         // output positions j0..j0+3
    const int r = rg * 8 + lr;             // source row index = (b*S+s)*H + h
    const int b = r / (Sc * Hc);
    const int rem = r - b * Sc * Hc;
    const int s = rem / Hc;
    const int h = rem - s * Hc;
    const size_t orow = ((size_t)(b * Hc + h) * Sc + s) * Dc;

    float outK[4], outV[4];
    #pragma unroll
    for (int e = 0; e < 4; ++e) {
        const int i = j0 + e;
        // K perm: [8c + 2t + e'] <- d = 8c + t + 4e'
        int c = i >> 3, tt = (i >> 1) & 3, ee = i & 1;
        outK[e] = __uint_as_float(f2tf(stK[lr * 128 + 8 * c + tt + 4 * ee]));
        // V perm: [g*16 + ot] <- d = 8*ot + g
        int gg = i >> 4, ot = i & 15;
        outV[e] = __uint_as_float(f2tf(stV[lr * 128 + 8 * ot + gg]));
    }
    *reinterpret_cast<float4*>(&g_Kf[orow + j0]) = *reinterpret_cast<float4*>(outK);
    *reinterpret_cast<float4*>(&g_Vf[orow + j0]) = *reinterpret_cast<float4*>(outV);
}

// ---------------- main kernel ------------------------------------------------
__global__ __launch_bounds__(128) void fa_tf32_kernel(
    const float* __restrict__ Q, float* __restrict__ O)
{
    extern __shared__ float smem[];

    const int tid  = threadIdx.x;
    const int warp = tid >> 5;
    const int lane = tid & 31;
    const int g = lane >> 2;
    const int t = lane & 3;

    const int qtile = (gridDim.x - 1) - blockIdx.x;   // heavy blocks first
    const int bh = blockIdx.y;
    const int b = bh >> 4;
    const int h = bh & 15;
    const int q0 = qtile * BM + warp * 16;

    const float scale = 0.08838834764831845f * 1.4426950408889634f; // /sqrt(D)*log2e

    // Q fragments: 16 k-chunks of m16n8k8 A frags (tf32, pre-scaled)
    uint32_t qa[16][4];
    {
        const float* qp = Q + ((size_t)(b * Sc + q0) * Hc + h) * Dc;
        #pragma unroll
        for (int c = 0; c < 16; ++c) {
            int d0 = c * 8 + t;
            qa[c][0] = f2tf(qp[(size_t)g       * HD + d0    ] * scale);
            qa[c][1] = f2tf(qp[(size_t)(g + 8) * HD + d0    ] * scale);
            qa[c][2] = f2tf(qp[(size_t)g       * HD + d0 + 4] * scale);
            qa[c][3] = f2tf(qp[(size_t)(g + 8) * HD + d0 + 4] * scale);
        }
    }

    float o[16][4];
    #pragma unroll
    for (int i = 0; i < 16; ++i) { o[i][0]=0.f; o[i][1]=0.f; o[i][2]=0.f; o[i][3]=0.f; }
    float m0 = -1e30f, m1 = -1e30f, l0 = 0.f, l1 = 0.f;

    const int nkt = 2 * qtile + 2;
    const float* kf = g_Kf + (size_t)(b * Hc + h) * Sc * Dc;
    const float* vf = g_Vf + (size_t)(b * Hc + h) * Sc * Dc;

    uint32_t sbase;
    { uint64_t a = __cvta_generic_to_shared(smem); sbase = (uint32_t)a; }

    // issue cp.async for one KV tile into buffer `buf`
    auto load_tile = [&](int buf, int kv0) {
        const uint32_t sK = sbase + (uint32_t)(buf * BUFF) * 4u;
        const uint32_t sV = sK + (uint32_t)(BN * KS) * 4u;
        const char* ksrc = (const char*)(kf + (size_t)kv0 * Dc);
        const char* vsrc = (const char*)(vf + (size_t)kv0 * Dc);
        #pragma unroll
        for (int i = 0; i < 8; ++i) {
            int chunk = i * 128 + tid;
            int row = chunk >> 5, col = chunk & 31;
            cpa16(sK + row * (KS * 4) + col * 16, ksrc + chunk * 16);
        }
        #pragma unroll
        for (int i = 0; i < 8; ++i) {
            int chunk = i * 128 + tid;
            int row = chunk >> 5, col = chunk & 31;
            cpa16(sV + row * (VS * 4) + col * 16, vsrc + chunk * 16);
        }
        asm volatile("cp.async.commit_group;");
    };

    load_tile(0, 0);

    for (int kt = 0; kt < nkt; ++kt) {
        const int kv0 = kt * BN;
        const int cur = kt & 1;

        if (kt + 1 < nkt) {
            load_tile(cur ^ 1, kv0 + BN);
            asm volatile("cp.async.wait_group 1;");
        } else {
            asm volatile("cp.async.wait_group 0;");
        }
        __syncthreads();

        const float* Ksm = smem + cur * BUFF;
        const float* Vsm = Ksm + BN * KS;

        // ---- S = Q K^T : 64 LDS.64 + 64 mma
        float sc[4][4];
        #pragma unroll
        for (int nt = 0; nt < 4; ++nt) {
            sc[nt][0]=0.f; sc[nt][1]=0.f; sc[nt][2]=0.f; sc[nt][3]=0.f;
            const float2* krow = reinterpret_cast<const float2*>(Ksm + (nt * 8 + g) * KS);
            #pragma unroll
            for (int c = 0; c < 16; ++c) {
                float2 kb = krow[c * 4 + t];   // (.x = d=8c+t, .y = d=8c+t+4)
                mma8(sc[nt], qa[c], __float_as_uint(kb.x), __float_as_uint(kb.y));
            }
        }

        // ---- causal mask
        if (kv0 + BN - 1 > q0) {
            #pragma unroll
            for (int nt = 0; nt < 4; ++nt) {
                int kb = kv0 + nt * 8 + 2 * t;
                if (kb     > q0 + g)     sc[nt][0] = -1e30f;
                if (kb + 1 > q0 + g)     sc[nt][1] = -1e30f;
                if (kb     > q0 + g + 8) sc[nt][2] = -1e30f;
                if (kb + 1 > q0 + g + 8) sc[nt][3] = -1e30f;
            }
        }

        // ---- online softmax (rows g and g+8 per thread)
        float mg0 = -1e30f, mg1 = -1e30f;
        #pragma unroll
        for (int nt = 0; nt < 4; ++nt) {
            mg0 = fmaxf(mg0, fmaxf(sc[nt][0], sc[nt][1]));
            mg1 = fmaxf(mg1, fmaxf(sc[nt][2], sc[nt][3]));
        }
        mg0 = fmaxf(mg0, __shfl_xor_sync(0xffffffffu, mg0, 1));
        mg0 = fmaxf(mg0, __shfl_xor_sync(0xffffffffu, mg0, 2));
        mg1 = fmaxf(mg1, __shfl_xor_sync(0xffffffffu, mg1, 1));
        mg1 = fmaxf(mg1, __shfl_xor_sync(0xffffffffu, mg1, 2));

        float m0n = fmaxf(m0, mg0);
        float m1n = fmaxf(m1, mg1);
        float a0 = ex2f(m0 - m0n);
        float a1 = ex2f(m1 - m1n);
        m0 = m0n; m1 = m1n;

        float r0 = 0.f, r1 = 0.f;
        #pragma unroll
        for (int nt = 0; nt < 4; ++nt) {
            sc[nt][0] = ex2f(sc[nt][0] - m0n);
            sc[nt][1] = ex2f(sc[nt][1] - m0n);
            sc[nt][2] = ex2f(sc[nt][2] - m1n);
            sc[nt][3] = ex2f(sc[nt][3] - m1n);
            r0 += sc[nt][0] + sc[nt][1];
            r1 += sc[nt][2] + sc[nt][3];
        }
        r0 += __shfl_xor_sync(0xffffffffu, r0, 1);
        r0 += __shfl_xor_sync(0xffffffffu, r0, 2);
        r1 += __shfl_xor_sync(0xffffffffu, r1, 1);
        r1 += __shfl_xor_sync(0xffffffffu, r1, 2);
        l0 = l0 * a0 + r0;
        l1 = l1 * a1 + r1;

        #pragma unroll
        for (int i = 0; i < 16; ++i) {
            o[i][0] *= a0; o[i][1] *= a0;
            o[i][2] *= a1; o[i][3] *= a1;
        }

        // ---- O += P V : remap P C-frag -> A-frag, 32 LDS.128 + 64 mma
        #pragma unroll
        for (int kc = 0; kc < 4; ++kc) {
            int src = (lane & ~3) | (t >> 1);
            float v0 = __shfl_sync(0xffffffffu, sc[kc][0], src);
            float v1 = __shfl_sync(0xffffffffu, sc[kc][1], src);
            float v2 = __shfl_sync(0xffffffffu, sc[kc][2], src);
            float v3 = __shfl_sync(0xffffffffu, sc[kc][3], src);
            float w0 = __shfl_sync(0xffffffffu, sc[kc][0], src + 2);
            float w1 = __shfl_sync(0xffffffffu, sc[kc][1], src + 2);
            float w2 = __shfl_sync(0xffffffffu, sc[kc][2], src + 2);
            float w3 = __shfl_sync(0xffffffffu, sc[kc][3], src + 2);
            uint32_t pa[4];
            bool odd = (t & 1) != 0;
            pa[0] = f2tf(odd ? v1 : v0);  // (row g,   key t)
            pa[1] = f2tf(odd ? v3 : v2);  // (row g+8, key t)
            pa[2] = f2tf(odd ? w1 : w0);  // (row g,   key t+4)
            pa[3] = f2tf(odd ? w3 : w2);  // (row g+8, key t+4)
            const float* v0p = Vsm + (kc * 8 + t) * VS + g * 16;   // perm: [g*16+ot]
            const float* v1p = v0p + 4 * VS;
            #pragma unroll
            for (int oc = 0; oc < 4; ++oc) {
                float4 B0 = *reinterpret_cast<const float4*>(v0p + oc * 4);
                float4 B1 = *reinterpret_cast<const float4*>(v1p + oc * 4);
                mma8(o[oc * 4 + 0], pa, __float_as_uint(B0.x), __float_as_uint(B1.x));
                mma8(o[oc * 4 + 1], pa, __float_as_uint(B0.y), __float_as_uint(B1.y));
                mma8(o[oc * 4 + 2], pa, __float_as_uint(B0.z), __float_as_uint(B1.z));
                mma8(o[oc * 4 + 3], pa, __float_as_uint(B0.w), __float_as_uint(B1.w));
            }
        }
        __syncthreads();   // all warps done with buf[cur] before it is refilled
    }

    // ---- normalize + store
    float inv0 = __frcp_rn(l0);
    float inv1 = __frcp_rn(l1);
    float* op = O + ((size_t)(b * Sc + q0) * Hc + h) * Dc;
    #pragma unroll
    for (int ot = 0; ot < 16; ++ot) {
        int d = ot * 8 + 2 * t;
        float2 r0v = make_float2(o[ot][0] * inv0, o[ot][1] * inv0);
        float2 r1v = make_float2(o[ot][2] * inv1, o[ot][3] * inv1);
        *reinterpret_cast<float2*>(op + (size_t)g       * HD + d) = r0v;
        *reinterpret_cast<float2*>(op + (size_t)(g + 8) * HD + d) = r1v;
    }
}

extern "C" void kernel_launch(void* const* d_in, const int* in_sizes, int n_in,
                              void* d_out, int out_size) {
    (void)in_sizes; (void)n_in; (void)out_size;
    const float* q = (const float*)d_in[0];
    const float* k = (const float*)d_in[1];
    const float* v = (const float*)d_in[2];
    float* out = (float*)d_out;

    cudaFuncSetAttribute(fa_tf32_kernel,
                         cudaFuncAttributeMaxDynamicSharedMemorySize, SMEM_BYTES);

    // prepass: 65536 rows of K+V, 8 rows per block
    prep_kernel<<<Bc * Sc * Hc / 8, 256>>>(k, v);

    dim3 grid(Sc / BM, Bc * Hc);
    fa_tf32_kernel<<<grid, 128, SMEM_BYTES>>>(q, out);
}